// round 7
// baseline (speedup 1.0000x reference)
#include <cuda_runtime.h>
#include <cuda_bf16.h>

// T=256, BS=128, N=2048. One persistent CTA per batch lane.
#define T_STEPS 256
#define BSZ     128
#define NFEAT   2048
#define BLOCK   128
#define EPT     16                 // elements per thread
#define PAIRS   (EPT / 2)          // 8 packed f32x2 pairs
#define NWARP   (BLOCK / 32)       // 4 warps
#define NPART   (2 * NWARP)        // 8 partials (4-level butterfly, parity halves)
#define FUDGE_C 1e-4f

typedef unsigned long long ull;

static __device__ __forceinline__ ull pack2(float lo, float hi) {
    ull r; asm("mov.b64 %0, {%1, %2};" : "=l"(r) : "f"(lo), "f"(hi)); return r;
}
static __device__ __forceinline__ ull bcast2(float v) { return pack2(v, v); }
static __device__ __forceinline__ float2 unpack2(ull v) {
    float2 r; asm("mov.b64 {%0, %1}, %2;" : "=f"(r.x), "=f"(r.y) : "l"(v)); return r;
}
static __device__ __forceinline__ ull fma2(ull a, ull b, ull c) {
    ull d; asm("fma.rn.f32x2 %0, %1, %2, %3;" : "=l"(d) : "l"(a), "l"(b), "l"(c)); return d;
}
static __device__ __forceinline__ ull add2(ull a, ull b) {
    ull d; asm("add.rn.f32x2 %0, %1, %2;" : "=l"(d) : "l"(a), "l"(b)); return d;
}
static __device__ __forceinline__ ull relu2(ull v) {
    float2 f = unpack2(v);
    return pack2(fmaxf(f.x, 0.0f), fmaxf(f.y, 0.0f));
}

__global__ __launch_bounds__(BLOCK, 1)
void elbo_scan_kernel(const float* __restrict__ noises,   // [T,BS]
                      const float* __restrict__ ys,       // [T,BS]
                      const float* __restrict__ qs,       // [T,BS]
                      const float* __restrict__ z_biases, // [N]
                      const float* __restrict__ w_in,     // [N]
                      const float* __restrict__ w_inq,    // [N]
                      const float* __restrict__ p_llr,
                      const float* __restrict__ p_llrd,
                      const float* __restrict__ p_sigb,
                      const float* __restrict__ p_os,
                      const float* __restrict__ p_ufs,
                      const float* __restrict__ p_spwd,
                      const float* __restrict__ p_qsc,
                      const float* __restrict__ p_tq,
                      const float* __restrict__ p_ty,
                      const float* __restrict__ p_te,
                      float* __restrict__ out)            // [T,BS]
{
    const int b    = blockIdx.x;
    const int tid  = threadIdx.x;
    const int wid  = tid >> 5;
    const int lane = tid & 31;

    __shared__ float s_y[T_STEPS];
    __shared__ float s_n[T_STEPS];
    __shared__ float s_q[T_STEPS];
    __shared__ ull   s_pu[2][NPART];    // packed (sW, sH) partials, double-buffered
    __shared__ float s_ph[2][NPART];    // s2 = sum(h^2) partials

    s_y[tid]         = ys[tid * BSZ + b];
    s_y[tid + BLOCK] = ys[(tid + BLOCK) * BSZ + b];
    s_n[tid]         = noises[tid * BSZ + b];
    s_n[tid + BLOCK] = noises[(tid + BLOCK) * BSZ + b];
    s_q[tid]         = qs[tid * BSZ + b];
    s_q[tid + BLOCK] = qs[(tid + BLOCK) * BSZ + b];

    const float lr0   = expf(p_llr[0]);
    const float lrd   = expf(p_llrd[0]);
    const float sigb  = p_sigb[0];
    const float osc   = p_os[0];
    const float ufsm1 = p_ufs[0] - 1.0f;
    const float spwd  = log1pf(expf(p_spwd[0]));
    const float qsc   = p_qsc[0];
    const float tq    = 1.0f + log1pf(expf(p_tq[0]));
    const float ty    = 1.0f + log1pf(expf(p_ty[0]));
    const float te    = 1.0f + log1pf(expf(p_te[0]));
    const float itq = 1.0f / tq, ctq = 1.0f - itq;
    const float ity = 1.0f / ty, cty = 1.0f - ity;
    const float ite = 1.0f / te, cte = 1.0f - ite;

    // Register-resident slices (packed f32x2).
    ull win2[PAIRS], wiq2[PAIRS], bia2[PAIRS], W2[PAIRS], hv[PAIRS], hnew[PAIRS], A2[PAIRS];
    {
        const int base = tid * EPT;
        const float4* w4 = reinterpret_cast<const float4*>(w_in + base);
        const float4* q4 = reinterpret_cast<const float4*>(w_inq + base);
        const float4* z4 = reinterpret_cast<const float4*>(z_biases + base);
        #pragma unroll
        for (int v = 0; v < EPT / 4; ++v) {
            float4 a = w4[v], c = q4[v], z = z4[v];
            win2[2*v]   = pack2(a.x, a.y);  win2[2*v+1] = pack2(a.z, a.w);
            wiq2[2*v]   = pack2(c.x, c.y);  wiq2[2*v+1] = pack2(c.z, c.w);
            bia2[2*v]   = pack2(sigb * z.x, sigb * z.y);
            bia2[2*v+1] = pack2(sigb * z.z, sigb * z.w);
        }
    }
    #pragma unroll
    for (int k = 0; k < PAIRS; ++k) W2[k] = 0ull;

    __syncthreads();

    // ---------------- Prologue: step-0 partials + prep for step 1 ----------------
    float lrmult = 1.0f, ylp = 0.0f, elp = 0.0f, cW = 1.0f, le_prev = 0.0f;
    float qlp = s_q[0] * itq;
    {
        const ull x2  = bcast2(s_n[0]);                // x_0 = noise_0 (u=e=0)
        const ull cq2 = bcast2(qsc * qlp);
        ull a20 = 0ull, a21 = 0ull;
        #pragma unroll
        for (int k = 0; k < PAIRS; ++k) {
            ull h = relu2(fma2(win2[k], x2, fma2(cq2, wiq2[k], bia2[k])));
            hv[k] = h;
            if (k & 1) a21 = fma2(h, h, a21); else a20 = fma2(h, h, a20);
        }
        float2 f2 = unpack2(add2(a20, a21));
        float s2 = f2.x + f2.y;
        #pragma unroll
        for (int off = 16; off >= 2; off >>= 1)
            s2 += __shfl_xor_sync(0xFFFFFFFFu, s2, off);
        if (lane < 2) {
            s_pu[0][(wid << 1) | lane] = 0ull;          // sW = sH = 0 at t=0
            s_ph[0][(wid << 1) | lane] = s2;
        }
    }
    // Prep for step 0's scalar chain + step-1 h (ax/bx/A2) — ylp_{-1} = 0.
    float y_c    = s_y[0];
    bool  flag_c = ((__float_as_uint(y_c) & 0x7FFFFFFFu) > 0x7F800000u);
    float byl_c  = 0.0f;
    float ax_c   = ufsm1 + (flag_c ? ity : 0.0f);
    float bx_c   = (flag_c ? 0.0f : ity * y_c) + byl_c + s_n[1];
    qlp = fmaf(ctq, qlp, s_q[1] * itq);
    {
        const ull cq2 = bcast2(qsc * qlp);
        #pragma unroll
        for (int k = 0; k < PAIRS; ++k) A2[k] = fma2(cq2, wiq2[k], bia2[k]);
    }

    // ---------------- Main loop: iteration t consumes step-t partials ----------------
    for (int t = 0; t < T_STEPS; ++t) {
        const int buf = t & 1;
        __syncthreads();                       // step-t partials visible

        // Critical combine: 8 packed (sW,sH) partials via LDS.128 + add2 tree.
        const longlong2* pu = reinterpret_cast<const longlong2*>(s_pu[buf]);
        longlong2 a0 = pu[0], a1 = pu[1], a2 = pu[2], a3 = pu[3];
        ull rA = add2(add2((ull)a0.x, (ull)a0.y), add2((ull)a1.x, (ull)a1.y));
        ull rB = add2(add2((ull)a2.x, (ull)a2.y), add2((ull)a3.x, (ull)a3.y));
        float2 swh = unpack2(add2(rA, rB));    // (sumW, sumH)

        // un_t = cW_t * sumW + le_{t-1} * sumH   (scalars from prev iteration)
        const float un = fmaf(cW, swh.x, le_prev * swh.y);
        if (tid == 0) out[t * BSZ + b] = osc * un;

        // x_{t+1} broadcast: one FMA off un.
        const ull x2 = bcast2(fmaf(ax_c, un, bx_c));

        // Off-critical combine: sum(h^2) for the scalar chain.
        const float4* ph = reinterpret_cast<const float4*>(s_ph[buf]);
        float4 hA = ph[0], hB = ph[1];
        const float sumh = ((hA.x + hA.y) + (hA.z + hA.w)) + ((hB.x + hB.y) + (hB.z + hB.w));

        // Fused: h_{t+1} + three accumulations (NO dependence on this step's scalar chain).
        ull aW0 = 0ull, aW1 = 0ull, aH0 = 0ull, aH1 = 0ull, a20 = 0ull, a21 = 0ull;
        #pragma unroll
        for (int k = 0; k < PAIRS; ++k) {
            ull h = relu2(fma2(win2[k], x2, A2[k]));
            hnew[k] = h;
            if (k & 1) { aW1 = fma2(W2[k], h, aW1); aH1 = fma2(hv[k], h, aH1); a21 = fma2(h, h, a21); }
            else       { aW0 = fma2(W2[k], h, aW0); aH0 = fma2(hv[k], h, aH0); a20 = fma2(h, h, a20); }
        }
        float2 fW = unpack2(add2(aW0, aW1));
        float2 fH = unpack2(add2(aH0, aH1));
        float2 f2 = unpack2(add2(a20, a21));
        float sW = fW.x + fW.y;
        float sH = fH.x + fH.y;
        float s2 = f2.x + f2.y;

        // 4-level butterfly, three interleaved chains; lanes 0/1 hold parity halves.
        #pragma unroll
        for (int off = 16; off >= 2; off >>= 1) {
            sW += __shfl_xor_sync(0xFFFFFFFFu, sW, off);
            sH += __shfl_xor_sync(0xFFFFFFFFu, sH, off);
            s2 += __shfl_xor_sync(0xFFFFFFFFu, s2, off);
        }
        if (lane < 2) {
            s_pu[buf ^ 1][(wid << 1) | lane] = pack2(sW, sH);
            s_ph[buf ^ 1][(wid << 1) | lane] = s2;
        }

        // -------- Shadow work (overlaps the shfl latency / barrier wait) --------
        // Scalar chain for step t.
        const float ysel = flag_c ? un : y_c;
        const float ylpn = fmaf(ity, ysel, byl_c);
        const float en   = ylpn - un;
        ylp = ylpn;
        elp = fmaf(cte, elp, en * ite);
        const float lr = lr0 * lrmult;
        const float le = lr * elp;
        const float v  = fmaf(le * le, sumh, FUDGE_C);
        lrmult *= __expf(-lrd * (v * __frsqrt_rn(v)));
        cW *= fmaf(-lr, spwd, 1.0f);
        const ull leoc2 = bcast2(__fdividef(le, cW));
        le_prev = le;

        // W2_{t+1} = W2_t + leoc_t * h_t; rotate h.
        #pragma unroll
        for (int k = 0; k < PAIRS; ++k) {
            W2[k] = fma2(leoc2, hv[k], W2[k]);
            hv[k] = hnew[k];
        }

        // Prep for next iteration (step t+1 scalar chain, step t+2 h).
        const int ti = (t + 1 < T_STEPS) ? (t + 1) : t;
        const int tn = (t + 2 < T_STEPS) ? (t + 2) : (T_STEPS - 1);
        y_c    = s_y[ti];
        flag_c = ((__float_as_uint(y_c) & 0x7FFFFFFFu) > 0x7F800000u);
        byl_c  = cty * ylp;
        ax_c   = ufsm1 + (flag_c ? ity : 0.0f);
        bx_c   = (flag_c ? 0.0f : ity * y_c) + byl_c + s_n[tn];
        qlp = fmaf(ctq, qlp, s_q[tn] * itq);
        const ull cq2 = bcast2(qsc * qlp);
        #pragma unroll
        for (int k = 0; k < PAIRS; ++k) A2[k] = fma2(cq2, wiq2[k], bia2[k]);
    }
}

extern "C" void kernel_launch(void* const* d_in, const int* in_sizes, int n_in,
                              void* d_out, int out_size)
{
    const float* noises = (const float*)d_in[1];
    const float* ys     = (const float*)d_in[2];
    const float* qs     = (const float*)d_in[3];
    const float* zb     = (const float*)d_in[4];
    const float* w_in   = (const float*)d_in[5];
    const float* w_inq  = (const float*)d_in[6];

    elbo_scan_kernel<<<BSZ, BLOCK>>>(noises, ys, qs, zb, w_in, w_inq,
                                     (const float*)d_in[7],  (const float*)d_in[8],
                                     (const float*)d_in[9],  (const float*)d_in[10],
                                     (const float*)d_in[11], (const float*)d_in[12],
                                     (const float*)d_in[13], (const float*)d_in[14],
                                     (const float*)d_in[15], (const float*)d_in[16],
                                     (float*)d_out);
}

// round 9
// speedup vs baseline: 1.1281x; 1.1281x over previous
#include <cuda_runtime.h>
#include <cuda_bf16.h>

// T=256, BS=128, N=2048. One persistent CTA per batch lane.
#define T_STEPS 256
#define BSZ     128
#define NFEAT   2048
#define BLOCK   128
#define EPT     16                 // elements per thread
#define PAIRS   (EPT / 2)          // 8 packed f32x2 pairs
#define NWARP   (BLOCK / 32)       // 4 warps
#define FUDGE_C 1e-4f

typedef unsigned long long ull;

static __device__ __forceinline__ ull pack2(float lo, float hi) {
    ull r; asm("mov.b64 %0, {%1, %2};" : "=l"(r) : "f"(lo), "f"(hi)); return r;
}
static __device__ __forceinline__ ull bcast2(float v) { return pack2(v, v); }
static __device__ __forceinline__ float2 unpack2(ull v) {
    float2 r; asm("mov.b64 {%0, %1}, %2;" : "=f"(r.x), "=f"(r.y) : "l"(v)); return r;
}
static __device__ __forceinline__ ull fma2(ull a, ull b, ull c) {
    ull d; asm("fma.rn.f32x2 %0, %1, %2, %3;" : "=l"(d) : "l"(a), "l"(b), "l"(c)); return d;
}
static __device__ __forceinline__ ull add2(ull a, ull b) {
    ull d; asm("add.rn.f32x2 %0, %1, %2;" : "=l"(d) : "l"(a), "l"(b)); return d;
}
static __device__ __forceinline__ ull relu2(ull v) {
    float2 f = unpack2(v);
    return pack2(fmaxf(f.x, 0.0f), fmaxf(f.y, 0.0f));
}

__global__ __launch_bounds__(BLOCK, 1)
void elbo_scan_kernel(const float* __restrict__ noises,   // [T,BS]
                      const float* __restrict__ ys,       // [T,BS]
                      const float* __restrict__ qs,       // [T,BS]
                      const float* __restrict__ z_biases, // [N]
                      const float* __restrict__ w_in,     // [N]
                      const float* __restrict__ w_inq,    // [N]
                      const float* __restrict__ p_llr,
                      const float* __restrict__ p_llrd,
                      const float* __restrict__ p_sigb,
                      const float* __restrict__ p_os,
                      const float* __restrict__ p_ufs,
                      const float* __restrict__ p_spwd,
                      const float* __restrict__ p_qsc,
                      const float* __restrict__ p_tq,
                      const float* __restrict__ p_ty,
                      const float* __restrict__ p_te,
                      float* __restrict__ out)            // [T,BS]
{
    const int b    = blockIdx.x;
    const int tid  = threadIdx.x;
    const int wid  = tid >> 5;
    const int lane = tid & 31;

    __shared__ float s_y[T_STEPS];
    __shared__ float s_n[T_STEPS];
    __shared__ float s_q[T_STEPS];
    __shared__ ull   s_p[2][2 * NWARP];    // double-buffered packed (au,ah) partials

    s_y[tid]         = ys[tid * BSZ + b];
    s_y[tid + BLOCK] = ys[(tid + BLOCK) * BSZ + b];
    s_n[tid]         = noises[tid * BSZ + b];
    s_n[tid + BLOCK] = noises[(tid + BLOCK) * BSZ + b];
    s_q[tid]         = qs[tid * BSZ + b];
    s_q[tid + BLOCK] = qs[(tid + BLOCK) * BSZ + b];

    const float lr0   = expf(p_llr[0]);
    const float lrd   = expf(p_llrd[0]);
    const float sigb  = p_sigb[0];
    const float osc   = p_os[0];
    const float ufsm1 = p_ufs[0] - 1.0f;
    const float spwd  = log1pf(expf(p_spwd[0]));
    const float qsc   = p_qsc[0];
    const float tq    = 1.0f + log1pf(expf(p_tq[0]));
    const float ty    = 1.0f + log1pf(expf(p_ty[0]));
    const float te    = 1.0f + log1pf(expf(p_te[0]));
    const float itq = 1.0f / tq, ctq = 1.0f - itq;
    const float ity = 1.0f / ty, cty = 1.0f - ity;
    const float ite = 1.0f / te, cte = 1.0f - ite;

    // Register-resident per-thread slices, packed f32x2.
    ull win2[PAIRS], wiq2[PAIRS], bia2[PAIRS], W2[PAIRS], A2[PAIRS];
    {
        const int base = tid * EPT;
        const float4* w4 = reinterpret_cast<const float4*>(w_in + base);
        const float4* q4 = reinterpret_cast<const float4*>(w_inq + base);
        const float4* z4 = reinterpret_cast<const float4*>(z_biases + base);
        #pragma unroll
        for (int v = 0; v < EPT / 4; ++v) {
            float4 a = w4[v], c = q4[v], z = z4[v];
            win2[2*v]   = pack2(a.x, a.y);  win2[2*v+1] = pack2(a.z, a.w);
            wiq2[2*v]   = pack2(c.x, c.y);  wiq2[2*v+1] = pack2(c.z, c.w);
            bia2[2*v]   = pack2(sigb * z.x, sigb * z.y);
            bia2[2*v+1] = pack2(sigb * z.z, sigb * z.w);
        }
    }
    #pragma unroll
    for (int k = 0; k < PAIRS; ++k) W2[k] = 0ull;

    __syncthreads();

    // Replicated scalar state.
    float lrmult = 1.0f, ylp = 0.0f, elp = 0.0f;
    // One-step-ahead scalars (all known before step t's reduction lands):
    float lr_c = lr0;                                  // lr_t
    float cW   = 1.0f;                                 // cW_t   (w_out_t = cW_t * W2)
    float cWn  = fmaf(-lr_c, spwd, 1.0f);              // cW_{t+1}
    float icWn = __fdividef(1.0f, cWn);                // 1 / cW_{t+1}
    float qlp = s_q[0] * itq;
    {   // A for step 0
        const ull cq2 = bcast2(qsc * qlp);
        #pragma unroll
        for (int k = 0; k < PAIRS; ++k) A2[k] = fma2(cq2, wiq2[k], bia2[k]);
    }
    ull x2 = bcast2(s_n[0]);               // x_0 = noise_0 (u=0, e=0)

    #pragma unroll 2
    for (int t = 0; t < T_STEPS; ++t) {
        // --- Elementwise: h_t, dot(W,h), sum(h^2). W is already W_t. ---
        ull hv[PAIRS];
        ull au0 = 0ull, au1 = 0ull, ah0 = 0ull, ah1 = 0ull;
        #pragma unroll
        for (int k = 0; k < PAIRS; ++k) {
            ull h = relu2(fma2(win2[k], x2, A2[k]));
            hv[k] = h;
            if (k & 1) { au1 = fma2(W2[k], h, au1); ah1 = fma2(h, h, ah1); }
            else       { au0 = fma2(W2[k], h, au0); ah0 = fma2(h, h, ah0); }
        }
        float2 auf = unpack2(add2(au0, au1));
        float2 ahf = unpack2(add2(ah0, ah1));
        float au_s = auf.x + auf.y;
        float ah_s = ahf.x + ahf.y;

        // --- 4-level butterfly (two interleaved chains); lanes 0/1 hold parity halves. ---
        #pragma unroll
        for (int off = 16; off >= 2; off >>= 1) {
            au_s += __shfl_xor_sync(0xFFFFFFFFu, au_s, off);
            ah_s += __shfl_xor_sync(0xFFFFFFFFu, ah_s, off);
        }
        const int buf = t & 1;
        if (lane < 2) s_p[buf][(wid << 1) | lane] = pack2(au_s, ah_s);

        // --- Latency-shadow prep for step t+1 (independent of the reduction). ---
        const int  tn   = (t + 1 < T_STEPS) ? (t + 1) : t;
        const float y   = s_y[t];
        const bool flag = ((__float_as_uint(y) & 0x7FFFFFFFu) > 0x7F800000u); // isnan
        const float byl = cty * ylp;
        const float ax  = ufsm1 + (flag ? ity : 0.0f);                // x_{t+1} = ax*u_t + bx
        const float bx  = (flag ? 0.0f : ity * y) + byl + s_n[tn];
        qlp = fmaf(ctq, qlp, s_q[tn] * itq);
        const ull cq2 = bcast2(qsc * qlp);
        #pragma unroll
        for (int k = 0; k < PAIRS; ++k) A2[k] = fma2(cq2, wiq2[k], bia2[k]);

        __syncthreads();                    // the only barrier per step

        // --- Redundant combine: 4 LDS.128 of packed partials + add2 tree. ---
        const longlong2* pp = reinterpret_cast<const longlong2*>(s_p[buf]);
        longlong2 l0 = pp[0], l1 = pp[1], l2 = pp[2], l3 = pp[3];
        ull rA = add2(add2((ull)l0.x, (ull)l0.y), add2((ull)l1.x, (ull)l1.y));
        ull rB = add2(add2((ull)l2.x, (ull)l2.y), add2((ull)l3.x, (ull)l3.y));
        float2 s = unpack2(add2(rA, rB));
        const float sumu = s.x, sumh = s.y;

        const float un = cW * sumu;                         // u_t
        x2 = bcast2(fmaf(ax, un, bx));                      // x_{t+1}: 1 FMA off un

        if (tid == 0) out[t * BSZ + b] = osc * un;

        // --- Short pure-FMA chain to leoc (lr_c, icWn precomputed last iter). ---
        const float ysel = flag ? un : y;
        const float ylpn = fmaf(ity, ysel, byl);
        const float en   = ylpn - un;
        ylp = ylpn;
        elp = fmaf(cte, elp, en * ite);
        const float le   = lr_c * elp;
        const ull leoc2  = bcast2(le * icWn);               // no MUFU on this path

        // --- Deferred W update with h_t still live in registers. ---
        #pragma unroll
        for (int k = 0; k < PAIRS; ++k) W2[k] = fma2(leoc2, hv[k], W2[k]);

        // --- Shadow: MUFU-heavy one-step-ahead scalars (slack >= 150 cy). ---
        const float v = fmaf(le * le, sumh, FUDGE_C);
        lrmult *= __expf(-lrd * (v * __frsqrt_rn(v)));      // exp(-lrd*sqrt(v))
        lr_c = lr0 * lrmult;                                // lr_{t+1}
        cW   = cWn;                                         // cW_{t+1}
        cWn  = cW * fmaf(-lr_c, spwd, 1.0f);                // cW_{t+2}
        icWn = __fdividef(1.0f, cWn);
    }
}

extern "C" void kernel_launch(void* const* d_in, const int* in_sizes, int n_in,
                              void* d_out, int out_size)
{
    const float* noises = (const float*)d_in[1];
    const float* ys     = (const float*)d_in[2];
    const float* qs     = (const float*)d_in[3];
    const float* zb     = (const float*)d_in[4];
    const float* w_in   = (const float*)d_in[5];
    const float* w_inq  = (const float*)d_in[6];

    elbo_scan_kernel<<<BSZ, BLOCK>>>(noises, ys, qs, zb, w_in, w_inq,
                                     (const float*)d_in[7],  (const float*)d_in[8],
                                     (const float*)d_in[9],  (const float*)d_in[10],
                                     (const float*)d_in[11], (const float*)d_in[12],
                                     (const float*)d_in[13], (const float*)d_in[14],
                                     (const float*)d_in[15], (const float*)d_in[16],
                                     (float*)d_out);
}

// round 10
// speedup vs baseline: 1.1328x; 1.0042x over previous
#include <cuda_runtime.h>
#include <cuda_bf16.h>

// T=256, BS=128, N=2048. One persistent CTA per batch lane.
#define T_STEPS 256
#define BSZ     128
#define NFEAT   2048
#define BLOCK   128
#define EPT     16                 // elements per thread
#define PAIRS   (EPT / 2)          // 8 packed f32x2 pairs
#define NWARP   (BLOCK / 32)       // 4 warps
#define NPART   (4 * NWARP)        // 16 partials (3-level butterfly, lanes 0-3)
#define FUDGE_C 1e-4f

typedef unsigned long long ull;

static __device__ __forceinline__ ull pack2(float lo, float hi) {
    ull r; asm("mov.b64 %0, {%1, %2};" : "=l"(r) : "f"(lo), "f"(hi)); return r;
}
static __device__ __forceinline__ ull bcast2(float v) { return pack2(v, v); }
static __device__ __forceinline__ float2 unpack2(ull v) {
    float2 r; asm("mov.b64 {%0, %1}, %2;" : "=f"(r.x), "=f"(r.y) : "l"(v)); return r;
}
static __device__ __forceinline__ ull fma2(ull a, ull b, ull c) {
    ull d; asm("fma.rn.f32x2 %0, %1, %2, %3;" : "=l"(d) : "l"(a), "l"(b), "l"(c)); return d;
}
static __device__ __forceinline__ ull add2(ull a, ull b) {
    ull d; asm("add.rn.f32x2 %0, %1, %2;" : "=l"(d) : "l"(a), "l"(b)); return d;
}
static __device__ __forceinline__ ull relu2(ull v) {
    float2 f = unpack2(v);
    return pack2(fmaxf(f.x, 0.0f), fmaxf(f.y, 0.0f));
}

__global__ __launch_bounds__(BLOCK, 1)
void elbo_scan_kernel(const float* __restrict__ noises,   // [T,BS]
                      const float* __restrict__ ys,       // [T,BS]
                      const float* __restrict__ qs,       // [T,BS]
                      const float* __restrict__ z_biases, // [N]
                      const float* __restrict__ w_in,     // [N]
                      const float* __restrict__ w_inq,    // [N]
                      const float* __restrict__ p_llr,
                      const float* __restrict__ p_llrd,
                      const float* __restrict__ p_sigb,
                      const float* __restrict__ p_os,
                      const float* __restrict__ p_ufs,
                      const float* __restrict__ p_spwd,
                      const float* __restrict__ p_qsc,
                      const float* __restrict__ p_tq,
                      const float* __restrict__ p_ty,
                      const float* __restrict__ p_te,
                      float* __restrict__ out)            // [T,BS]
{
    const int b    = blockIdx.x;
    const int tid  = threadIdx.x;
    const int wid  = tid >> 5;
    const int lane = tid & 31;

    __shared__ float s_y[T_STEPS];
    __shared__ float s_n[T_STEPS];
    __shared__ float s_q[T_STEPS];
    __shared__ ull   s_p[2][NPART];    // double-buffered packed (au,ah) partials

    s_y[tid]         = ys[tid * BSZ + b];
    s_y[tid + BLOCK] = ys[(tid + BLOCK) * BSZ + b];
    s_n[tid]         = noises[tid * BSZ + b];
    s_n[tid + BLOCK] = noises[(tid + BLOCK) * BSZ + b];
    s_q[tid]         = qs[tid * BSZ + b];
    s_q[tid + BLOCK] = qs[(tid + BLOCK) * BSZ + b];

    const float lr0   = expf(p_llr[0]);
    const float lrd   = expf(p_llrd[0]);
    const float sigb  = p_sigb[0];
    const float osc   = p_os[0];
    const float ufsm1 = p_ufs[0] - 1.0f;
    const float spwd  = log1pf(expf(p_spwd[0]));
    const float qsc   = p_qsc[0];
    const float tq    = 1.0f + log1pf(expf(p_tq[0]));
    const float ty    = 1.0f + log1pf(expf(p_ty[0]));
    const float te    = 1.0f + log1pf(expf(p_te[0]));
    const float itq = 1.0f / tq, ctq = 1.0f - itq;
    const float ity = 1.0f / ty, cty = 1.0f - ity;
    const float ite = 1.0f / te, cte = 1.0f - ite;

    // Register-resident per-thread slices, packed f32x2.
    ull win2[PAIRS], wiq2[PAIRS], bia2[PAIRS], W2[PAIRS], A2[PAIRS];
    {
        const int base = tid * EPT;
        const float4* w4 = reinterpret_cast<const float4*>(w_in + base);
        const float4* q4 = reinterpret_cast<const float4*>(w_inq + base);
        const float4* z4 = reinterpret_cast<const float4*>(z_biases + base);
        #pragma unroll
        for (int v = 0; v < EPT / 4; ++v) {
            float4 a = w4[v], c = q4[v], z = z4[v];
            win2[2*v]   = pack2(a.x, a.y);  win2[2*v+1] = pack2(a.z, a.w);
            wiq2[2*v]   = pack2(c.x, c.y);  wiq2[2*v+1] = pack2(c.z, c.w);
            bia2[2*v]   = pack2(sigb * z.x, sigb * z.y);
            bia2[2*v+1] = pack2(sigb * z.z, sigb * z.w);
        }
    }
    #pragma unroll
    for (int k = 0; k < PAIRS; ++k) W2[k] = 0ull;

    __syncthreads();

    // Replicated scalar state.
    float lrmult = 1.0f, ylp = 0.0f, elp = 0.0f;
    // One-step-ahead scalars (known before the reduction lands):
    float lr_c = lr0;                                  // lr_t
    float cW   = 1.0f;                                 // cW_t
    float cWn  = fmaf(-lr_c, spwd, 1.0f);              // cW_{t+1}
    float icWn = __fdividef(1.0f, cWn);                // 1/cW_{t+1}
    float qlp = s_q[0] * itq;
    {   // A for step 0
        const ull cq2 = bcast2(qsc * qlp);
        #pragma unroll
        for (int k = 0; k < PAIRS; ++k) A2[k] = fma2(cq2, wiq2[k], bia2[k]);
    }
    ull x2 = bcast2(s_n[0]);               // x_0 = noise_0 (u=0, e=0)

    #pragma unroll 2
    for (int t = 0; t < T_STEPS; ++t) {
        // --- Elementwise: h_t, dot(W,h), sum(h^2). W is already W_t. ---
        ull hv[PAIRS];
        ull au0 = 0ull, au1 = 0ull, ah0 = 0ull, ah1 = 0ull;
        #pragma unroll
        for (int k = 0; k < PAIRS; ++k) {
            ull h = relu2(fma2(win2[k], x2, A2[k]));
            hv[k] = h;
            if (k & 1) { au1 = fma2(W2[k], h, au1); ah1 = fma2(h, h, ah1); }
            else       { au0 = fma2(W2[k], h, au0); ah0 = fma2(h, h, ah0); }
        }
        float2 auf = unpack2(add2(au0, au1));
        float2 ahf = unpack2(add2(ah0, ah1));
        float au_s = auf.x + auf.y;
        float ah_s = ahf.x + ahf.y;

        // --- 3-level butterfly; lanes 0-3 hold the 4 residue classes (mod 4). ---
        #pragma unroll
        for (int off = 16; off >= 4; off >>= 1) {
            au_s += __shfl_xor_sync(0xFFFFFFFFu, au_s, off);
            ah_s += __shfl_xor_sync(0xFFFFFFFFu, ah_s, off);
        }
        const int buf = t & 1;
        if (lane < 4) s_p[buf][(wid << 2) | lane] = pack2(au_s, ah_s);

        // --- Latency-shadow prep: affine coefficients for the post-barrier chain. ---
        const int  tn   = (t + 1 < T_STEPS) ? (t + 1) : t;
        const float y   = s_y[t];
        const bool flag = ((__float_as_uint(y) & 0x7FFFFFFFu) > 0x7F800000u); // isnan
        const float byl = cty * ylp;
        // x_{t+1} = axc*sumu + bx    (cW folded into axc)
        const float axc = (ufsm1 + (flag ? ity : 0.0f)) * cW;
        const float bx  = (flag ? 0.0f : ity * y) + byl + s_n[tn];
        // en_t = aec*sumu + be       (en = ae*un + be, un = cW*sumu)
        const float aec = (flag ? (ity - 1.0f) : -1.0f) * cW;
        const float be  = (flag ? 0.0f : ity * y) + byl;
        const float belp = cte * elp;                  // elp_t = ite*en + belp
        const float lic  = lr_c * icWn;                // leoc = lic * elp_t
        qlp = fmaf(ctq, qlp, s_q[tn] * itq);
        const ull cq2 = bcast2(qsc * qlp);
        #pragma unroll
        for (int k = 0; k < PAIRS; ++k) A2[k] = fma2(cq2, wiq2[k], bia2[k]);

        __syncthreads();                    // the only barrier per step

        // --- Redundant combine: 8 LDS.128 of packed partials + add2 tree. ---
        const longlong2* pp = reinterpret_cast<const longlong2*>(s_p[buf]);
        longlong2 l0 = pp[0], l1 = pp[1], l2 = pp[2], l3 = pp[3];
        longlong2 l4 = pp[4], l5 = pp[5], l6 = pp[6], l7 = pp[7];
        ull r0 = add2(add2((ull)l0.x, (ull)l0.y), add2((ull)l1.x, (ull)l1.y));
        ull r1 = add2(add2((ull)l2.x, (ull)l2.y), add2((ull)l3.x, (ull)l3.y));
        ull r2 = add2(add2((ull)l4.x, (ull)l4.y), add2((ull)l5.x, (ull)l5.y));
        ull r3 = add2(add2((ull)l6.x, (ull)l6.y), add2((ull)l7.x, (ull)l7.y));
        float2 s = unpack2(add2(add2(r0, r1), add2(r2, r3)));
        const float sumu = s.x, sumh = s.y;

        // Short affine chains off sumu (no MUFU, no select on path).
        x2 = bcast2(fmaf(axc, sumu, bx));              // x_{t+1}
        const float en   = fmaf(aec, sumu, be);        // e_t
        const float elpn = fmaf(ite, en, belp);        // elp_t
        const ull leoc2  = bcast2(lic * elpn);         // W-update coeff
        elp = elpn;

        // --- Deferred W update with h_t still live in registers. ---
        #pragma unroll
        for (int k = 0; k < PAIRS; ++k) W2[k] = fma2(leoc2, hv[k], W2[k]);

        // --- Shadow: output, ylp, MUFU-heavy one-step-ahead scalars. ---
        const float un = cW * sumu;                    // u_t
        if (tid == 0) out[t * BSZ + b] = osc * un;
        const float ysel = flag ? un : y;
        ylp = fmaf(ity, ysel, byl);
        const float le = lr_c * elpn;
        const float v  = fmaf(le * le, sumh, FUDGE_C);
        lrmult *= __expf(-lrd * (v * __frsqrt_rn(v))); // exp(-lrd*sqrt(v))
        lr_c = lr0 * lrmult;                           // lr_{t+1}
        cW   = cWn;                                    // cW_{t+1}
        cWn  = cW * fmaf(-lr_c, spwd, 1.0f);           // cW_{t+2}
        icWn = __fdividef(1.0f, cWn);
    }
}

extern "C" void kernel_launch(void* const* d_in, const int* in_sizes, int n_in,
                              void* d_out, int out_size)
{
    const float* noises = (const float*)d_in[1];
    const float* ys     = (const float*)d_in[2];
    const float* qs     = (const float*)d_in[3];
    const float* zb     = (const float*)d_in[4];
    const float* w_in   = (const float*)d_in[5];
    const float* w_inq  = (const float*)d_in[6];

    elbo_scan_kernel<<<BSZ, BLOCK>>>(noises, ys, qs, zb, w_in, w_inq,
                                     (const float*)d_in[7],  (const float*)d_in[8],
                                     (const float*)d_in[9],  (const float*)d_in[10],
                                     (const float*)d_in[11], (const float*)d_in[12],
                                     (const float*)d_in[13], (const float*)d_in[14],
                                     (const float*)d_in[15], (const float*)d_in[16],
                                     (float*)d_out);
}

// round 11
// speedup vs baseline: 1.1687x; 1.0317x over previous
#include <cuda_runtime.h>
#include <cuda_bf16.h>

// T=256, BS=128, N=2048. One persistent CTA per batch lane.
#define T_STEPS 256
#define BSZ     128
#define NFEAT   2048
#define BLOCK   128
#define EPT     16                 // elements per thread
#define PAIRS   (EPT / 2)          // 8 packed f32x2 pairs
#define NWARP   (BLOCK / 32)       // 4 warps
#define NPART   (4 * NWARP)        // 16 partials (3-level butterfly, lanes 0-3)
#define FUDGE_C 1e-4f

typedef unsigned long long ull;

static __device__ __forceinline__ ull pack2(float lo, float hi) {
    ull r; asm("mov.b64 %0, {%1, %2};" : "=l"(r) : "f"(lo), "f"(hi)); return r;
}
static __device__ __forceinline__ ull bcast2(float v) { return pack2(v, v); }
static __device__ __forceinline__ float2 unpack2(ull v) {
    float2 r; asm("mov.b64 {%0, %1}, %2;" : "=f"(r.x), "=f"(r.y) : "l"(v)); return r;
}
static __device__ __forceinline__ ull fma2(ull a, ull b, ull c) {
    ull d; asm("fma.rn.f32x2 %0, %1, %2, %3;" : "=l"(d) : "l"(a), "l"(b), "l"(c)); return d;
}
static __device__ __forceinline__ ull add2(ull a, ull b) {
    ull d; asm("add.rn.f32x2 %0, %1, %2;" : "=l"(d) : "l"(a), "l"(b)); return d;
}
static __device__ __forceinline__ ull relu2(ull v) {
    float2 f = unpack2(v);
    return pack2(fmaxf(f.x, 0.0f), fmaxf(f.y, 0.0f));
}

__global__ __launch_bounds__(BLOCK, 1)
void elbo_scan_kernel(const float* __restrict__ noises,   // [T,BS]
                      const float* __restrict__ ys,       // [T,BS]
                      const float* __restrict__ qs,       // [T,BS]
                      const float* __restrict__ z_biases, // [N]
                      const float* __restrict__ w_in,     // [N]
                      const float* __restrict__ w_inq,    // [N]
                      const float* __restrict__ p_llr,
                      const float* __restrict__ p_llrd,
                      const float* __restrict__ p_sigb,
                      const float* __restrict__ p_os,
                      const float* __restrict__ p_ufs,
                      const float* __restrict__ p_spwd,
                      const float* __restrict__ p_qsc,
                      const float* __restrict__ p_tq,
                      const float* __restrict__ p_ty,
                      const float* __restrict__ p_te,
                      float* __restrict__ out)            // [T,BS]
{
    const int b    = blockIdx.x;
    const int tid  = threadIdx.x;
    const int wid  = tid >> 5;
    const int lane = tid & 31;

    __shared__ float s_y[T_STEPS];
    __shared__ float s_n[T_STEPS];
    __shared__ float s_q[T_STEPS];
    __shared__ ull   s_p[2][NPART];    // double-buffered packed (au,ah) partials

    s_y[tid]         = ys[tid * BSZ + b];
    s_y[tid + BLOCK] = ys[(tid + BLOCK) * BSZ + b];
    s_n[tid]         = noises[tid * BSZ + b];
    s_n[tid + BLOCK] = noises[(tid + BLOCK) * BSZ + b];
    s_q[tid]         = qs[tid * BSZ + b];
    s_q[tid + BLOCK] = qs[(tid + BLOCK) * BSZ + b];

    const float lr0   = expf(p_llr[0]);
    const float lrd   = expf(p_llrd[0]);
    const float sigb  = p_sigb[0];
    const float osc   = p_os[0];
    const float ufsm1 = p_ufs[0] - 1.0f;
    const float spwd  = log1pf(expf(p_spwd[0]));
    const float qsc   = p_qsc[0];
    const float tq    = 1.0f + log1pf(expf(p_tq[0]));
    const float ty    = 1.0f + log1pf(expf(p_ty[0]));
    const float te    = 1.0f + log1pf(expf(p_te[0]));
    const float itq = 1.0f / tq, ctq = 1.0f - itq;
    const float ity = 1.0f / ty, cty = 1.0f - ity;
    const float ite = 1.0f / te, cte = 1.0f - ite;

    // Register-resident per-thread slices, packed f32x2.
    ull win2[PAIRS], wiq2[PAIRS], bia2[PAIRS], W2[PAIRS], A2[PAIRS], hv[PAIRS];
    {
        const int base = tid * EPT;
        const float4* w4 = reinterpret_cast<const float4*>(w_in + base);
        const float4* q4 = reinterpret_cast<const float4*>(w_inq + base);
        const float4* z4 = reinterpret_cast<const float4*>(z_biases + base);
        #pragma unroll
        for (int v = 0; v < EPT / 4; ++v) {
            float4 a = w4[v], c = q4[v], z = z4[v];
            win2[2*v]   = pack2(a.x, a.y);  win2[2*v+1] = pack2(a.z, a.w);
            wiq2[2*v]   = pack2(c.x, c.y);  wiq2[2*v+1] = pack2(c.z, c.w);
            bia2[2*v]   = pack2(sigb * z.x, sigb * z.y);
            bia2[2*v+1] = pack2(sigb * z.z, sigb * z.w);
        }
    }
    #pragma unroll
    for (int k = 0; k < PAIRS; ++k) W2[k] = 0ull;

    __syncthreads();   // staged inputs visible

    // ---------------- Prologue: step-0 h/partials + coefs for iteration 0 ----------------
    float lrmult = 1.0f, ylp = 0.0f, elp = 0.0f;
    float lr_c = lr0;                                  // lr_t
    float cW   = 1.0f;                                 // cW_t
    float cWn  = fmaf(-lr_c, spwd, 1.0f);              // cW_{t+1}
    float icWn = __fdividef(1.0f, cWn);                // 1/cW_{t+1}
    float qlp  = s_q[0] * itq;
    {
        const ull x2  = bcast2(s_n[0]);                // x_0 = noise_0 (u=e=0)
        const ull cq2 = bcast2(qsc * qlp);
        ull ah0 = 0ull, ah1 = 0ull;
        #pragma unroll
        for (int k = 0; k < PAIRS; ++k) {
            ull h = relu2(fma2(win2[k], x2, fma2(cq2, wiq2[k], bia2[k])));
            hv[k] = h;
            if (k & 1) ah1 = fma2(h, h, ah1); else ah0 = fma2(h, h, ah0);
        }
        float2 f2 = unpack2(add2(ah0, ah1));
        float ah_s = f2.x + f2.y;
        #pragma unroll
        for (int off = 16; off >= 4; off >>= 1)
            ah_s += __shfl_xor_sync(0xFFFFFFFFu, ah_s, off);
        if (lane < 4) s_p[0][(wid << 2) | lane] = pack2(0.0f, ah_s);  // au_0 = 0
    }
    // Coefficients for iteration 0 (step-0 consumption; ylp_{-1}=elp_{-1}=0).
    float y_c    = s_y[0];
    bool  flag_c = ((__float_as_uint(y_c) & 0x7FFFFFFFu) > 0x7F800000u);
    float byl_c  = 0.0f;
    float axc_c  = (ufsm1 + (flag_c ? ity : 0.0f)) * cW;
    float bx_c   = (flag_c ? 0.0f : ity * y_c) + s_n[1];
    float aec_c  = (flag_c ? (ity - 1.0f) : -1.0f) * cW;
    float be_c   = (flag_c ? 0.0f : ity * y_c);
    float belp_c = 0.0f;
    float lic_c  = lr_c * icWn;
    // A for step 1 (consumed by iteration 0's h loop).
    qlp = fmaf(ctq, qlp, s_q[1] * itq);
    {
        const ull cq2 = bcast2(qsc * qlp);
        #pragma unroll
        for (int k = 0; k < PAIRS; ++k) A2[k] = fma2(cq2, wiq2[k], bia2[k]);
    }

    __syncthreads();   // s_p[0] visible; NOTHING sits between STS and this bar

    #pragma unroll 2
    for (int t = 0; t < T_STEPS; ++t) {
        const int buf = t & 1;

        // --- Combine step-t partials: 8 LDS.128 + add2 tree (broadcast reads). ---
        const longlong2* pp = reinterpret_cast<const longlong2*>(s_p[buf]);
        longlong2 l0 = pp[0], l1 = pp[1], l2 = pp[2], l3 = pp[3];
        longlong2 l4 = pp[4], l5 = pp[5], l6 = pp[6], l7 = pp[7];
        ull r0 = add2(add2((ull)l0.x, (ull)l0.y), add2((ull)l1.x, (ull)l1.y));
        ull r1 = add2(add2((ull)l2.x, (ull)l2.y), add2((ull)l3.x, (ull)l3.y));
        ull r2 = add2(add2((ull)l4.x, (ull)l4.y), add2((ull)l5.x, (ull)l5.y));
        ull r3 = add2(add2((ull)l6.x, (ull)l6.y), add2((ull)l7.x, (ull)l7.y));
        float2 s = unpack2(add2(add2(r0, r1), add2(r2, r3)));
        const float sumu = s.x, sumh = s.y;

        // --- Short affine chains off sumu (all coefs prepped last iteration). ---
        const float en   = fmaf(aec_c, sumu, be_c);     // e_t
        const float elpn = fmaf(ite, en, belp_c);       // elp_t
        const ull leoc2  = bcast2(lic_c * elpn);        // W-update coeff
        const ull x2     = bcast2(fmaf(axc_c, sumu, bx_c));   // x_{t+1}
        elp = elpn;

        // --- W_{t+1} update, h_{t+1}, partial dot/sumsq (fused). ---
        ull au0 = 0ull, au1 = 0ull, ah0 = 0ull, ah1 = 0ull;
        #pragma unroll
        for (int k = 0; k < PAIRS; ++k) {
            W2[k] = fma2(leoc2, hv[k], W2[k]);
            ull h = relu2(fma2(win2[k], x2, A2[k]));
            hv[k] = h;
            if (k & 1) { au1 = fma2(W2[k], h, au1); ah1 = fma2(h, h, ah1); }
            else       { au0 = fma2(W2[k], h, au0); ah0 = fma2(h, h, ah0); }
        }
        float2 auf = unpack2(add2(au0, au1));
        float2 ahf = unpack2(add2(ah0, ah1));
        float au_s = auf.x + auf.y;
        float ah_s = ahf.x + ahf.y;

        // --- 3-level butterfly; lanes 0-3 hold the 4 residue classes. ---
        #pragma unroll
        for (int off = 16; off >= 4; off >>= 1) {
            au_s += __shfl_xor_sync(0xFFFFFFFFu, au_s, off);
            ah_s += __shfl_xor_sync(0xFFFFFFFFu, ah_s, off);
        }

        // --- Tail: independent of the butterfly; issues inside its latency shadow. ---
        const float un = cW * sumu;                     // u_t
        if (tid == 0) out[t * BSZ + b] = osc * un;
        const float ysel = flag_c ? un : y_c;
        ylp = fmaf(ity, ysel, byl_c);                   // ylp_t
        const float le = lr_c * elpn;
        const float v  = fmaf(le * le, sumh, FUDGE_C);
        lrmult *= __expf(-lrd * (v * __frsqrt_rn(v)));  // exp(-lrd*sqrt(v))
        lr_c = lr0 * lrmult;                            // lr_{t+1}
        cW   = cWn;                                     // cW_{t+1}
        cWn  = cW * fmaf(-lr_c, spwd, 1.0f);            // cW_{t+2}
        icWn = __fdividef(1.0f, cWn);
        // Coefficients for iteration t+1 (step t+1 consumption).
        const int ti = (t + 1 < T_STEPS) ? (t + 1) : t;
        const int tn = (t + 2 < T_STEPS) ? (t + 2) : (T_STEPS - 1);
        y_c    = s_y[ti];
        flag_c = ((__float_as_uint(y_c) & 0x7FFFFFFFu) > 0x7F800000u);
        byl_c  = cty * ylp;
        axc_c  = (ufsm1 + (flag_c ? ity : 0.0f)) * cW;
        bx_c   = (flag_c ? 0.0f : ity * y_c) + byl_c + s_n[tn];
        aec_c  = (flag_c ? (ity - 1.0f) : -1.0f) * cW;
        be_c   = (flag_c ? 0.0f : ity * y_c) + byl_c;
        belp_c = cte * elpn;
        lic_c  = lr_c * icWn;
        qlp = fmaf(ctq, qlp, s_q[tn] * itq);            // qlp_{t+2}
        const ull cq2 = bcast2(qsc * qlp);
        #pragma unroll
        for (int k = 0; k < PAIRS; ++k) A2[k] = fma2(cq2, wiq2[k], bia2[k]);

        // --- STS then bar: nothing between them. ---
        if (lane < 4) s_p[buf ^ 1][(wid << 2) | lane] = pack2(au_s, ah_s);
        __syncthreads();
    }
}

extern "C" void kernel_launch(void* const* d_in, const int* in_sizes, int n_in,
                              void* d_out, int out_size)
{
    const float* noises = (const float*)d_in[1];
    const float* ys     = (const float*)d_in[2];
    const float* qs     = (const float*)d_in[3];
    const float* zb     = (const float*)d_in[4];
    const float* w_in   = (const float*)d_in[5];
    const float* w_inq  = (const float*)d_in[6];

    elbo_scan_kernel<<<BSZ, BLOCK>>>(noises, ys, qs, zb, w_in, w_inq,
                                     (const float*)d_in[7],  (const float*)d_in[8],
                                     (const float*)d_in[9],  (const float*)d_in[10],
                                     (const float*)d_in[11], (const float*)d_in[12],
                                     (const float*)d_in[13], (const float*)d_in[14],
                                     (const float*)d_in[15], (const float*)d_in[16],
                                     (float*)d_out);
}

// round 12
// speedup vs baseline: 1.2021x; 1.0285x over previous
#include <cuda_runtime.h>
#include <cuda_bf16.h>

// T=256, BS=128, N=2048. One persistent CTA per batch lane.
#define T_STEPS 256
#define BSZ     128
#define NFEAT   2048
#define BLOCK   128
#define EPT     16                 // elements per thread
#define PAIRS   (EPT / 2)          // 8 packed f32x2 pairs
#define NWARP   (BLOCK / 32)       // 4 warps
#define NPART   (4 * NWARP)        // 16 partials (3-level butterfly, lanes 0-3)
#define FUDGE_C 1e-4f

typedef unsigned long long ull;

static __device__ __forceinline__ ull pack2(float lo, float hi) {
    ull r; asm("mov.b64 %0, {%1, %2};" : "=l"(r) : "f"(lo), "f"(hi)); return r;
}
static __device__ __forceinline__ ull bcast2(float v) { return pack2(v, v); }
static __device__ __forceinline__ float2 unpack2(ull v) {
    float2 r; asm("mov.b64 {%0, %1}, %2;" : "=f"(r.x), "=f"(r.y) : "l"(v)); return r;
}
static __device__ __forceinline__ ull fma2(ull a, ull b, ull c) {
    ull d; asm("fma.rn.f32x2 %0, %1, %2, %3;" : "=l"(d) : "l"(a), "l"(b), "l"(c)); return d;
}
static __device__ __forceinline__ ull add2(ull a, ull b) {
    ull d; asm("add.rn.f32x2 %0, %1, %2;" : "=l"(d) : "l"(a), "l"(b)); return d;
}
static __device__ __forceinline__ ull relu2(ull v) {
    float2 f = unpack2(v);
    return pack2(fmaxf(f.x, 0.0f), fmaxf(f.y, 0.0f));
}

__global__ __launch_bounds__(BLOCK, 1)
void elbo_scan_kernel(const float* __restrict__ noises,   // [T,BS]
                      const float* __restrict__ ys,       // [T,BS]
                      const float* __restrict__ qs,       // [T,BS]
                      const float* __restrict__ z_biases, // [N]
                      const float* __restrict__ w_in,     // [N]
                      const float* __restrict__ w_inq,    // [N]
                      const float* __restrict__ p_llr,
                      const float* __restrict__ p_llrd,
                      const float* __restrict__ p_sigb,
                      const float* __restrict__ p_os,
                      const float* __restrict__ p_ufs,
                      const float* __restrict__ p_spwd,
                      const float* __restrict__ p_qsc,
                      const float* __restrict__ p_tq,
                      const float* __restrict__ p_ty,
                      const float* __restrict__ p_te,
                      float* __restrict__ out)            // [T,BS]
{
    const int b    = blockIdx.x;
    const int tid  = threadIdx.x;
    const int wid  = tid >> 5;
    const int lane = tid & 31;

    __shared__ float s_y[T_STEPS];
    __shared__ float s_n[T_STEPS];
    __shared__ float s_q[T_STEPS];
    __shared__ ull   s_p[2][NPART];    // double-buffered packed (au,ah) partials

    s_y[tid]         = ys[tid * BSZ + b];
    s_y[tid + BLOCK] = ys[(tid + BLOCK) * BSZ + b];
    s_n[tid]         = noises[tid * BSZ + b];
    s_n[tid + BLOCK] = noises[(tid + BLOCK) * BSZ + b];
    s_q[tid]         = qs[tid * BSZ + b];
    s_q[tid + BLOCK] = qs[(tid + BLOCK) * BSZ + b];

    const float lr0   = expf(p_llr[0]);
    const float lrd   = expf(p_llrd[0]);
    const float sigb  = p_sigb[0];
    const float osc   = p_os[0];
    const float ufsm1 = p_ufs[0] - 1.0f;
    const float spwd  = log1pf(expf(p_spwd[0]));
    const float qsc   = p_qsc[0];
    const float tq    = 1.0f + log1pf(expf(p_tq[0]));
    const float ty    = 1.0f + log1pf(expf(p_ty[0]));
    const float te    = 1.0f + log1pf(expf(p_te[0]));
    const float itq = 1.0f / tq, ctq = 1.0f - itq;
    const float ity = 1.0f / ty, cty = 1.0f - ity;
    const float ite = 1.0f / te, cte = 1.0f - ite;

    // Register-resident per-thread slices, packed f32x2.
    ull win2[PAIRS], wiq2[PAIRS], bia2[PAIRS], W2[PAIRS], A2[PAIRS], hv[PAIRS];
    {
        const int base = tid * EPT;
        const float4* w4 = reinterpret_cast<const float4*>(w_in + base);
        const float4* q4 = reinterpret_cast<const float4*>(w_inq + base);
        const float4* z4 = reinterpret_cast<const float4*>(z_biases + base);
        #pragma unroll
        for (int v = 0; v < EPT / 4; ++v) {
            float4 a = w4[v], c = q4[v], z = z4[v];
            win2[2*v]   = pack2(a.x, a.y);  win2[2*v+1] = pack2(a.z, a.w);
            wiq2[2*v]   = pack2(c.x, c.y);  wiq2[2*v+1] = pack2(c.z, c.w);
            bia2[2*v]   = pack2(sigb * z.x, sigb * z.y);
            bia2[2*v+1] = pack2(sigb * z.z, sigb * z.w);
        }
    }
    #pragma unroll
    for (int k = 0; k < PAIRS; ++k) W2[k] = 0ull;

    __syncthreads();   // staged inputs visible

    // ---------------- Prologue: step-0 h/partials + coefs for iteration 0 ----------------
    float lrmult = 1.0f, ylp = 0.0f;
    float lr_c = lr0;                                  // lr_t
    float cW   = 1.0f;                                 // cW_t
    float cWn  = fmaf(-lr_c, spwd, 1.0f);              // cW_{t+1}
    float icWn = __fdividef(1.0f, cWn);                // 1/cW_{t+1}
    float qlp  = s_q[0] * itq;
    {
        const ull x2  = bcast2(s_n[0]);                // x_0 = noise_0 (u=e=0)
        const ull cq2 = bcast2(qsc * qlp);
        ull ah0 = 0ull, ah1 = 0ull;
        #pragma unroll
        for (int k = 0; k < PAIRS; ++k) {
            ull h = relu2(fma2(win2[k], x2, fma2(cq2, wiq2[k], bia2[k])));
            hv[k] = h;
            if (k & 1) ah1 = fma2(h, h, ah1); else ah0 = fma2(h, h, ah0);
        }
        float2 f2 = unpack2(add2(ah0, ah1));
        float ah_s = f2.x + f2.y;
        #pragma unroll
        for (int off = 16; off >= 4; off >>= 1)
            ah_s += __shfl_xor_sync(0xFFFFFFFFu, ah_s, off);
        if (lane < 4) s_p[0][(wid << 2) | lane] = pack2(0.0f, ah_s);  // au_0 = 0
    }
    // Coefficients for iteration 0 (step-0 consumption; ylp_{-1}=elp_{-1}=0).
    float y_c    = s_y[0];
    bool  flag_c = ((__float_as_uint(y_c) & 0x7FFFFFFFu) > 0x7F800000u);
    float byl_c  = 0.0f;
    float axc_c  = (ufsm1 + (flag_c ? ity : 0.0f)) * cW;
    float bx_c   = (flag_c ? 0.0f : ity * y_c) + s_n[1];
    float aec_c  = (flag_c ? (ity - 1.0f) : -1.0f) * cW;
    float be_c   = (flag_c ? 0.0f : ity * y_c);
    float belp_c = 0.0f;
    float lic_c  = lr_c * icWn;
    // cq for step 1 (A2 prep happens at loop top, in the LDS shadow).
    qlp = fmaf(ctq, qlp, s_q[1] * itq);
    ull cq2_c = bcast2(qsc * qlp);

    __syncthreads();   // s_p[0] visible; NOTHING between STS and this bar

    #pragma unroll 2
    for (int t = 0; t < T_STEPS; ++t) {
        const int buf = t & 1;

        // --- Combine step-t partials (8 LDS.128 issue first; A2 prep fills the wait). ---
        const longlong2* pp = reinterpret_cast<const longlong2*>(s_p[buf]);
        longlong2 l0 = pp[0], l1 = pp[1], l2 = pp[2], l3 = pp[3];
        longlong2 l4 = pp[4], l5 = pp[5], l6 = pp[6], l7 = pp[7];

        // A2 for step t+1 (consumed by this iteration's hot loop below) —
        // independent of the LDS results, issues inside their latency shadow.
        #pragma unroll
        for (int k = 0; k < PAIRS; ++k) A2[k] = fma2(cq2_c, wiq2[k], bia2[k]);

        ull r0 = add2(add2((ull)l0.x, (ull)l0.y), add2((ull)l1.x, (ull)l1.y));
        ull r1 = add2(add2((ull)l2.x, (ull)l2.y), add2((ull)l3.x, (ull)l3.y));
        ull r2 = add2(add2((ull)l4.x, (ull)l4.y), add2((ull)l5.x, (ull)l5.y));
        ull r3 = add2(add2((ull)l6.x, (ull)l6.y), add2((ull)l7.x, (ull)l7.y));
        float2 s = unpack2(add2(add2(r0, r1), add2(r2, r3)));
        const float sumu = s.x, sumh = s.y;

        // --- Short affine chains off sumu (coefs prepped last iteration). ---
        const float en   = fmaf(aec_c, sumu, be_c);     // e_t
        const float elpn = fmaf(ite, en, belp_c);       // elp_t
        const ull leoc2  = bcast2(lic_c * elpn);        // W-update coeff
        const ull x2     = bcast2(fmaf(axc_c, sumu, bx_c));   // x_{t+1}

        // --- W_{t+1} update, h_{t+1}, partial dot/sumsq (fused). ---
        ull au0 = 0ull, au1 = 0ull, ah0 = 0ull, ah1 = 0ull;
        #pragma unroll
        for (int k = 0; k < PAIRS; ++k) {
            W2[k] = fma2(leoc2, hv[k], W2[k]);
            ull h = relu2(fma2(win2[k], x2, A2[k]));
            hv[k] = h;
            if (k & 1) { au1 = fma2(W2[k], h, au1); ah1 = fma2(h, h, ah1); }
            else       { au0 = fma2(W2[k], h, au0); ah0 = fma2(h, h, ah0); }
        }
        float2 auf = unpack2(add2(au0, au1));
        float2 ahf = unpack2(add2(ah0, ah1));
        float au_s = auf.x + auf.y;
        float ah_s = ahf.x + ahf.y;

        // --- 3-level butterfly; lanes 0-3 hold the 4 residue classes. ---
        #pragma unroll
        for (int off = 16; off >= 4; off >>= 1) {
            au_s += __shfl_xor_sync(0xFFFFFFFFu, au_s, off);
            ah_s += __shfl_xor_sync(0xFFFFFFFFu, ah_s, off);
        }

        // --- Tail (fits the shfl shadow now that A2 prep moved out). ---
        const float un = cW * sumu;                     // u_t
        if (tid == 0) out[t * BSZ + b] = osc * un;
        const float ysel = flag_c ? un : y_c;
        ylp = fmaf(ity, ysel, byl_c);                   // ylp_t
        const float le = lr_c * elpn;
        const float v  = fmaf(le * le, sumh, FUDGE_C);
        lrmult *= __expf(-lrd * (v * __frsqrt_rn(v)));  // exp(-lrd*sqrt(v))
        lr_c = lr0 * lrmult;                            // lr_{t+1}
        cW   = cWn;                                     // cW_{t+1}
        cWn  = cW * fmaf(-lr_c, spwd, 1.0f);            // cW_{t+2}
        icWn = __fdividef(1.0f, cWn);
        // Coefficients for iteration t+1 (step t+1 consumption).
        const int ti = (t + 1 < T_STEPS) ? (t + 1) : t;
        const int tn = (t + 2 < T_STEPS) ? (t + 2) : (T_STEPS - 1);
        y_c    = s_y[ti];
        flag_c = ((__float_as_uint(y_c) & 0x7FFFFFFFu) > 0x7F800000u);
        byl_c  = cty * ylp;
        axc_c  = (ufsm1 + (flag_c ? ity : 0.0f)) * cW;
        be_c   = (flag_c ? 0.0f : ity * y_c) + byl_c;
        bx_c   = be_c + s_n[tn];
        aec_c  = (flag_c ? (ity - 1.0f) : -1.0f) * cW;
        belp_c = cte * elpn;
        lic_c  = lr_c * icWn;
        qlp    = fmaf(ctq, qlp, s_q[tn] * itq);         // qlp_{t+2}
        cq2_c  = bcast2(qsc * qlp);

        // --- STS then bar: nothing between them. ---
        if (lane < 4) s_p[buf ^ 1][(wid << 2) | lane] = pack2(au_s, ah_s);
        __syncthreads();
    }
}

extern "C" void kernel_launch(void* const* d_in, const int* in_sizes, int n_in,
                              void* d_out, int out_size)
{
    const float* noises = (const float*)d_in[1];
    const float* ys     = (const float*)d_in[2];
    const float* qs     = (const float*)d_in[3];
    const float* zb     = (const float*)d_in[4];
    const float* w_in   = (const float*)d_in[5];
    const float* w_inq  = (const float*)d_in[6];

    elbo_scan_kernel<<<BSZ, BLOCK>>>(noises, ys, qs, zb, w_in, w_inq,
                                     (const float*)d_in[7],  (const float*)d_in[8],
                                     (const float*)d_in[9],  (const float*)d_in[10],
                                     (const float*)d_in[11], (const float*)d_in[12],
                                     (const float*)d_in[13], (const float*)d_in[14],
                                     (const float*)d_in[15], (const float*)d_in[16],
                                     (float*)d_out);
}